// round 2
// baseline (speedup 1.0000x reference)
#include <cuda_runtime.h>
#include <math.h>

// Shapes: B=2, L=512, C=64
// Inputs (metadata order):
// 0 pairwise_states [B,L,L,C] f32
// 1 attention_mask  [B,1,1,L] f32
// 2 ln_in_w [C]  3 ln_in_b [C]
// 4 W_lp 5 b_lp 6 W_rp 7 b_rp 8 W_lg 9 b_lg 10 W_rg 11 b_rg 12 W_og 13 b_og
// 14 ln_out_w 15 ln_out_b 16 W_out 17 b_out
// out [B,L,L,C] f32

static constexpr int BB = 2;
static constexpr int LDIM = 512;
static constexpr int CDIM = 64;
static constexpr size_t NFULL = (size_t)BB * LDIM * LDIM * CDIM; // 33,554,432

// Scratch (device globals; allocation APIs are forbidden)
__device__ float g_left [NFULL]; // [b][c][i][k] channel-major
__device__ float g_right[NFULL]; // [b][c][j][k] channel-major
__device__ float g_og   [NFULL]; // [b][i][j][c] row-major
__device__ float g_tri  [NFULL]; // [b][c][i][j] channel-major

__device__ __forceinline__ float sigmoidf_(float x) {
    return 1.0f / (1.0f + __expf(-x));
}

// ---------------------------------------------------------------------------
// Kernel A: LayerNorm + 5 projections (lp, rp, lg, rg, og) fused.
// Block = (kt, i, b): 64 rows (k = kt*64..kt*64+63) of the [b,i,:,:] slab.
// GEMM: X[64 rows x 64 c] @ W[64 c x 5*64 outs], 256 threads,
// each thread: 8 rows x 2 cols x 5 projections = 80 accumulators.
// Stores left/right transposed (channel-major) for the triangle GEMM.
// ---------------------------------------------------------------------------
__global__ void __launch_bounds__(256, 1) kernA(
    const float* __restrict__ x, const float* __restrict__ mask,
    const float* __restrict__ lnw, const float* __restrict__ lnbv,
    const float* __restrict__ Wlp, const float* __restrict__ blp,
    const float* __restrict__ Wrp, const float* __restrict__ brp,
    const float* __restrict__ Wlg, const float* __restrict__ blg,
    const float* __restrict__ Wrg, const float* __restrict__ brg,
    const float* __restrict__ Wog, const float* __restrict__ bog)
{
    extern __shared__ float sm[];
    float* Ws   = sm;            // 5*64*64 = 20480
    float* bs   = Ws + 20480;    // 320
    float* Xraw = bs + 320;      // 64*65 = 4160
    float* Xs   = Xraw + 4160;   // 64*72 = 4608 (transposed, [c][row])

    const int tid = threadIdx.x;
    const int lane = tid & 31;
    const int warp = tid >> 5;
    const int kt = blockIdx.x, i = blockIdx.y, b = blockIdx.z;

    // Load weights/biases into smem (L2-resident, coalesced)
    {
        const float* Wsrc[5] = {Wlp, Wrp, Wlg, Wrg, Wog};
        #pragma unroll
        for (int p = 0; p < 5; ++p) {
            const float* __restrict__ src = Wsrc[p];
            for (int e = tid; e < 4096; e += 256) Ws[p * 4096 + e] = src[e];
        }
        const float* bsrc[5] = {blp, brp, blg, brg, bog};
        #pragma unroll
        for (int p = 0; p < 5; ++p)
            if (tid < 64) bs[p * 64 + tid] = bsrc[p][tid];
    }
    // Load 64 input rows (contiguous 16KB)
    {
        size_t xbase = (((size_t)b * LDIM + i) * LDIM + (size_t)kt * 64) * CDIM;
        for (int e = tid; e < 4096; e += 256)
            Xraw[(e >> 6) * 65 + (e & 63)] = x[xbase + e];
    }
    __syncthreads();

    // LayerNorm per row: warp handles 8 rows; lane owns channels lane, lane+32.
    {
        const float lw0 = lnw[lane], lw1 = lnw[lane + 32];
        const float lb0 = lnbv[lane], lb1 = lnbv[lane + 32];
        #pragma unroll
        for (int u = 0; u < 8; ++u) {
            int r = warp * 8 + u;
            float x0 = Xraw[r * 65 + lane];
            float x1 = Xraw[r * 65 + lane + 32];
            float s = x0 + x1;
            #pragma unroll
            for (int o = 16; o; o >>= 1) s += __shfl_xor_sync(0xffffffffu, s, o);
            float mu = s * (1.0f / 64.0f);
            float d0 = x0 - mu, d1 = x1 - mu;
            float v = d0 * d0 + d1 * d1;
            #pragma unroll
            for (int o = 16; o; o >>= 1) v += __shfl_xor_sync(0xffffffffu, v, o);
            float rinv = rsqrtf(v * (1.0f / 64.0f) + 1e-5f);
            Xs[lane * 72 + r]        = d0 * rinv * lw0 + lb0;
            Xs[(lane + 32) * 72 + r] = d1 * rinv * lw1 + lb1;
        }
    }
    __syncthreads();

    // GEMM: rows warp*8..+7, cols lane & lane+32 of each of 5 projections
    float acc[5][8][2];
    #pragma unroll
    for (int p = 0; p < 5; ++p)
        #pragma unroll
        for (int u = 0; u < 8; ++u) { acc[p][u][0] = 0.f; acc[p][u][1] = 0.f; }

    #pragma unroll 4
    for (int c = 0; c < 64; ++c) {
        float4 a0 = *(const float4*)&Xs[c * 72 + warp * 8];
        float4 a1 = *(const float4*)&Xs[c * 72 + warp * 8 + 4];
        float a[8] = {a0.x, a0.y, a0.z, a0.w, a1.x, a1.y, a1.z, a1.w};
        #pragma unroll
        for (int p = 0; p < 5; ++p) {
            float w0 = Ws[p * 4096 + c * 64 + lane];
            float w1 = Ws[p * 4096 + c * 64 + lane + 32];
            #pragma unroll
            for (int u = 0; u < 8; ++u) {
                acc[p][u][0] += a[u] * w0;
                acc[p][u][1] += a[u] * w1;
            }
        }
    }

    // Epilogue: mask, gates, transposed stores
    const float mv = mask[b * LDIM + i];
    #pragma unroll
    for (int u = 0; u < 8; ++u) {
        int r = warp * 8 + u;
        int k = kt * 64 + r;
        #pragma unroll
        for (int h = 0; h < 2; ++h) {
            int c = lane + h * 32;
            float lp = acc[0][u][h] + bs[c];
            float rp = acc[1][u][h] + bs[64 + c];
            float lg = acc[2][u][h] + bs[128 + c];
            float rg = acc[3][u][h] + bs[192 + c];
            float oz = acc[4][u][h] + bs[256 + c];
            size_t cix = (((size_t)(b * 64 + c)) * LDIM + i) * LDIM + k;
            g_left[cix]  = lp * mv * sigmoidf_(lg);
            g_right[cix] = rp * mv * sigmoidf_(rg);
            g_og[(((size_t)b * LDIM + i) * LDIM + k) * CDIM + c] = sigmoidf_(oz);
        }
    }
}

// ---------------------------------------------------------------------------
// Kernel B: triangle update as 128 independent 512x512x512 NT SGEMMs.
// out[i][j] = sum_k L[i][k] * R[j][k], per (b,c) channel matrix.
// 128x128 block tile, BK=8, 256 threads, 8x8 microtile, double-buffered smem.
// ---------------------------------------------------------------------------
__global__ void __launch_bounds__(256, 2) kernB()
{
    __shared__ float As[2][8][128];
    __shared__ float Bs[2][8][128];

    const int m = blockIdx.z;                 // (b*64 + c)
    const float* __restrict__ Lm = g_left  + (size_t)m * (LDIM * LDIM);
    const float* __restrict__ Rm = g_right + (size_t)m * (LDIM * LDIM);
    float* __restrict__ Om       = g_tri   + (size_t)m * (LDIM * LDIM);

    const int i0 = blockIdx.y * 128;
    const int j0 = blockIdx.x * 128;
    const int tid = threadIdx.x;
    const int tx = tid & 15;       // column micro-tile (8 cols)
    const int ty = tid >> 4;       // row micro-tile (8 rows)
    const int lrow = tid >> 1;     // load row 0..127
    const int lk = (tid & 1) * 4;  // load k offset 0 or 4

    float acc[8][8];
    #pragma unroll
    for (int a = 0; a < 8; ++a)
        #pragma unroll
        for (int bcol = 0; bcol < 8; ++bcol) acc[a][bcol] = 0.f;

    // preload tile 0
    {
        float4 pa = *(const float4*)&Lm[(size_t)(i0 + lrow) * LDIM + lk];
        float4 pb = *(const float4*)&Rm[(size_t)(j0 + lrow) * LDIM + lk];
        As[0][lk + 0][lrow] = pa.x; As[0][lk + 1][lrow] = pa.y;
        As[0][lk + 2][lrow] = pa.z; As[0][lk + 3][lrow] = pa.w;
        Bs[0][lk + 0][lrow] = pb.x; Bs[0][lk + 1][lrow] = pb.y;
        Bs[0][lk + 2][lrow] = pb.z; Bs[0][lk + 3][lrow] = pb.w;
    }
    __syncthreads();

    for (int t = 0; t < 64; ++t) {
        const int cur = t & 1;
        float4 na, nb;
        if (t < 63) {
            int k0 = (t + 1) * 8 + lk;
            na = *(const float4*)&Lm[(size_t)(i0 + lrow) * LDIM + k0];
            nb = *(const float4*)&Rm[(size_t)(j0 + lrow) * LDIM + k0];
        }
        #pragma unroll
        for (int kk = 0; kk < 8; ++kk) {
            float4 a0 = *(const float4*)&As[cur][kk][ty * 8];
            float4 a1 = *(const float4*)&As[cur][kk][ty * 8 + 4];
            float4 b0 = *(const float4*)&Bs[cur][kk][tx * 8];
            float4 b1 = *(const float4*)&Bs[cur][kk][tx * 8 + 4];
            float av[8] = {a0.x, a0.y, a0.z, a0.w, a1.x, a1.y, a1.z, a1.w};
            float bv[8] = {b0.x, b0.y, b0.z, b0.w, b1.x, b1.y, b1.z, b1.w};
            #pragma unroll
            for (int mi = 0; mi < 8; ++mi)
                #pragma unroll
                for (int ni = 0; ni < 8; ++ni)
                    acc[mi][ni] += av[mi] * bv[ni];
        }
        if (t < 63) {
            const int nxt = cur ^ 1;
            As[nxt][lk + 0][lrow] = na.x; As[nxt][lk + 1][lrow] = na.y;
            As[nxt][lk + 2][lrow] = na.z; As[nxt][lk + 3][lrow] = na.w;
            Bs[nxt][lk + 0][lrow] = nb.x; Bs[nxt][lk + 1][lrow] = nb.y;
            Bs[nxt][lk + 2][lrow] = nb.z; Bs[nxt][lk + 3][lrow] = nb.w;
            __syncthreads();
        }
    }

    #pragma unroll
    for (int mi = 0; mi < 8; ++mi) {
        int row = i0 + ty * 8 + mi;
        float4 o0 = make_float4(acc[mi][0], acc[mi][1], acc[mi][2], acc[mi][3]);
        float4 o1 = make_float4(acc[mi][4], acc[mi][5], acc[mi][6], acc[mi][7]);
        *(float4*)&Om[(size_t)row * LDIM + j0 + tx * 8]     = o0;
        *(float4*)&Om[(size_t)row * LDIM + j0 + tx * 8 + 4] = o1;
    }
}

// ---------------------------------------------------------------------------
// Kernel C: y = LN(tri)*og @ W_out + b_out + residual
// Block = (jt, i, b): 64 output positions j. Gathers tri from channel-major,
// LN over c, gates with og, 64x64 GEMM with W_out, adds residual.
// ---------------------------------------------------------------------------
__global__ void __launch_bounds__(256, 2) kernC(
    const float* __restrict__ resid,
    const float* __restrict__ lnw, const float* __restrict__ lnbv,
    const float* __restrict__ Wout, const float* __restrict__ bout,
    float* __restrict__ out)
{
    extern __shared__ float sm[];
    float* Wo = sm;           // 4096
    float* bo = Wo + 4096;    // 64
    float* Tc = bo + 64;      // 64*65 = 4160  (tri gather, [c][j], pad 65)
    float* Gs = Tc + 4160;    // 64*72 = 4608  (gated LN, [c][j], pad 72)

    const int tid = threadIdx.x;
    const int lane = tid & 31;
    const int warp = tid >> 5;
    const int jt = blockIdx.x, i = blockIdx.y, b = blockIdx.z;

    for (int e = tid; e < 4096; e += 256) Wo[e] = Wout[e];
    if (tid < 64) bo[tid] = bout[tid];
    for (int e = tid; e < 4096; e += 256) {
        int c = e >> 6, j = e & 63;
        Tc[c * 65 + j] =
            g_tri[(((size_t)(b * 64 + c)) * LDIM + i) * LDIM + jt * 64 + j];
    }
    __syncthreads();

    const size_t rowbase = (((size_t)b * LDIM + i) * LDIM + (size_t)jt * 64) * CDIM;
    {
        const float lw0 = lnw[lane], lw1 = lnw[lane + 32];
        const float lb0 = lnbv[lane], lb1 = lnbv[lane + 32];
        #pragma unroll
        for (int u = 0; u < 8; ++u) {
            int j = warp * 8 + u;
            float t0 = Tc[lane * 65 + j];
            float t1 = Tc[(lane + 32) * 65 + j];
            float s = t0 + t1;
            #pragma unroll
            for (int o = 16; o; o >>= 1) s += __shfl_xor_sync(0xffffffffu, s, o);
            float mu = s * (1.0f / 64.0f);
            float d0 = t0 - mu, d1 = t1 - mu;
            float v = d0 * d0 + d1 * d1;
            #pragma unroll
            for (int o = 16; o; o >>= 1) v += __shfl_xor_sync(0xffffffffu, v, o);
            float rinv = rsqrtf(v * (1.0f / 64.0f) + 1e-5f);
            float g0 = (d0 * rinv * lw0 + lb0) * g_og[rowbase + (size_t)j * CDIM + lane];
            float g1 = (d1 * rinv * lw1 + lb1) * g_og[rowbase + (size_t)j * CDIM + lane + 32];
            Gs[lane * 72 + j] = g0;
            Gs[(lane + 32) * 72 + j] = g1;
        }
    }
    __syncthreads();

    float acc[8][2];
    #pragma unroll
    for (int u = 0; u < 8; ++u) { acc[u][0] = 0.f; acc[u][1] = 0.f; }

    #pragma unroll 4
    for (int c = 0; c < 64; ++c) {
        float4 a0 = *(const float4*)&Gs[c * 72 + warp * 8];
        float4 a1 = *(const float4*)&Gs[c * 72 + warp * 8 + 4];
        float a[8] = {a0.x, a0.y, a0.z, a0.w, a1.x, a1.y, a1.z, a1.w};
        float w0 = Wo[c * 64 + lane];
        float w1 = Wo[c * 64 + lane + 32];
        #pragma unroll
        for (int u = 0; u < 8; ++u) {
            acc[u][0] += a[u] * w0;
            acc[u][1] += a[u] * w1;
        }
    }

    #pragma unroll
    for (int u = 0; u < 8; ++u) {
        int j = warp * 8 + u;
        size_t o0 = rowbase + (size_t)j * CDIM + lane;
        out[o0]      = acc[u][0] + bo[lane]      + resid[o0];
        out[o0 + 32] = acc[u][1] + bo[lane + 32] + resid[o0 + 32];
    }
}

// ---------------------------------------------------------------------------

extern "C" void kernel_launch(void* const* d_in, const int* in_sizes, int n_in,
                              void* d_out, int out_size)
{
    const float* x    = (const float*)d_in[0];
    const float* msk  = (const float*)d_in[1];
    const float* liw  = (const float*)d_in[2];
    const float* lib  = (const float*)d_in[3];
    const float* Wlp  = (const float*)d_in[4];
    const float* blp  = (const float*)d_in[5];
    const float* Wrp  = (const float*)d_in[6];
    const float* brp  = (const float*)d_in[7];
    const float* Wlg  = (const float*)d_in[8];
    const float* blg  = (const float*)d_in[9];
    const float* Wrg  = (const float*)d_in[10];
    const float* brg  = (const float*)d_in[11];
    const float* Wog  = (const float*)d_in[12];
    const float* bog  = (const float*)d_in[13];
    const float* low  = (const float*)d_in[14];
    const float* lob  = (const float*)d_in[15];
    const float* Wout = (const float*)d_in[16];
    const float* bout = (const float*)d_in[17];
    float* out = (float*)d_out;

    const int SMEM_A = (20480 + 320 + 4160 + 4608) * 4; // 118272 B
    const int SMEM_C = (4096 + 64 + 4160 + 4608) * 4;   //  51712 B
    cudaFuncSetAttribute(kernA, cudaFuncAttributeMaxDynamicSharedMemorySize, SMEM_A);
    cudaFuncSetAttribute(kernC, cudaFuncAttributeMaxDynamicSharedMemorySize, SMEM_C);

    dim3 gridA(LDIM / 64, LDIM, BB);
    kernA<<<gridA, 256, SMEM_A>>>(x, msk, liw, lib,
                                  Wlp, blp, Wrp, brp, Wlg, blg, Wrg, brg, Wog, bog);

    dim3 gridB(LDIM / 128, LDIM / 128, BB * CDIM);
    kernB<<<gridB, 256>>>();

    dim3 gridC(LDIM / 64, LDIM, BB);
    kernC<<<gridC, 256, SMEM_C>>>(x, low, lob, Wout, bout, out);
}

// round 3
// speedup vs baseline: 1.8543x; 1.8543x over previous
#include <cuda_runtime.h>
#include <math.h>
#include <stdint.h>

// Shapes: B=2, L=512, C=64
// Inputs (metadata order):
// 0 pairwise_states [B,L,L,C] f32
// 1 attention_mask  [B,1,1,L] f32
// 2 ln_in_w [C]  3 ln_in_b [C]
// 4 W_lp 5 b_lp 6 W_rp 7 b_rp 8 W_lg 9 b_lg 10 W_rg 11 b_rg 12 W_og 13 b_og
// 14 ln_out_w 15 ln_out_b 16 W_out 17 b_out
// out [B,L,L,C] f32

static constexpr int BB = 2;
static constexpr int LDIM = 512;
static constexpr int CDIM = 64;
static constexpr size_t NFULL = (size_t)BB * LDIM * LDIM * CDIM; // 33,554,432

// Scratch (device globals; allocation APIs are forbidden)
__device__ float g_left [NFULL]; // [b][c][i][k] channel-major, tf32-rounded
__device__ float g_right[NFULL]; // [b][c][j][k] channel-major, tf32-rounded
__device__ float g_og   [NFULL]; // [b][i][j][c] row-major
__device__ float g_tri  [NFULL]; // [b][c][i][j] channel-major

__device__ __forceinline__ float sigmoidf_(float x) {
    return 1.0f / (1.0f + __expf(-x));
}

__device__ __forceinline__ float f2tf32(float f) {
    uint32_t u;
    asm("cvt.rna.tf32.f32 %0, %1;" : "=r"(u) : "f"(f));
    return __uint_as_float(u);
}

__device__ __forceinline__ void mma_tf32(float* d, const uint32_t* a, const uint32_t* b) {
    asm volatile(
        "mma.sync.aligned.m16n8k8.row.col.f32.tf32.tf32.f32 "
        "{%0,%1,%2,%3}, {%4,%5,%6,%7}, {%8,%9}, {%0,%1,%2,%3};"
        : "+f"(d[0]), "+f"(d[1]), "+f"(d[2]), "+f"(d[3])
        : "r"(a[0]), "r"(a[1]), "r"(a[2]), "r"(a[3]), "r"(b[0]), "r"(b[1]));
}

// ---------------------------------------------------------------------------
// Kernel A: LayerNorm + 5 projections (lp, rp, lg, rg, og) fused.
// Block = (i, b). Weights loaded to smem ONCE per block; loop over 8 k-tiles
// of 64 rows. 512 threads. Left/right written channel-major via smem
// transpose (coalesced 256B segments), pre-rounded to tf32 for kernB.
// ---------------------------------------------------------------------------
__global__ void __launch_bounds__(512, 1) kernA(
    const float* __restrict__ x, const float* __restrict__ mask,
    const float* __restrict__ lnw, const float* __restrict__ lnbv,
    const float* __restrict__ Wlp, const float* __restrict__ blp,
    const float* __restrict__ Wrp, const float* __restrict__ brp,
    const float* __restrict__ Wlg, const float* __restrict__ blg,
    const float* __restrict__ Wrg, const float* __restrict__ brg,
    const float* __restrict__ Wog, const float* __restrict__ bog)
{
    extern __shared__ float sm[];
    float* Ws     = sm;             // 5*4096 = 20480
    float* bs     = Ws + 20480;     // 320
    float* region = bs + 320;       // 8512 floats, unioned:
    float* Xraw   = region;         //   [64 rows][pitch 65]  (4160)
    float* Xs     = region + 4160;  //   [64 c][pitch 68]     (4352)
    float* Lt     = region;         //   [64 c][pitch 66]     (4224)
    float* Rt     = region + 4224;  //   [64 c][pitch 66]     (4224)

    const int tid  = threadIdx.x;
    const int lane = tid & 31;
    const int warp = tid >> 5;      // 0..15
    const int i = blockIdx.x, b = blockIdx.y;

    // Load weights/biases into smem once
    {
        const float* Wsrc[5] = {Wlp, Wrp, Wlg, Wrg, Wog};
        #pragma unroll
        for (int p = 0; p < 5; ++p) {
            const float* __restrict__ src = Wsrc[p];
            for (int e = tid; e < 4096; e += 512) Ws[p * 4096 + e] = src[e];
        }
        const float* bsrc[5] = {blp, brp, blg, brg, bog};
        #pragma unroll
        for (int p = 0; p < 5; ++p)
            if (tid < 64) bs[p * 64 + tid] = bsrc[p][tid];
    }

    const float mv  = mask[b * LDIM + i];
    const float lw0 = lnw[lane],  lw1 = lnw[lane + 32];
    const float lb0 = lnbv[lane], lb1 = lnbv[lane + 32];
    __syncthreads();

    for (int kt = 0; kt < 8; ++kt) {
        // Load 64 input rows (16KB contiguous)
        {
            size_t xbase = (((size_t)b * LDIM + i) * LDIM + (size_t)kt * 64) * CDIM;
            for (int e = tid; e < 4096; e += 512)
                Xraw[(e >> 6) * 65 + (e & 63)] = x[xbase + e];
        }
        __syncthreads();

        // LayerNorm: warp handles rows 4*warp..4*warp+3; lane owns c = lane, lane+32
        #pragma unroll
        for (int u = 0; u < 4; ++u) {
            int r = warp * 4 + u;
            float x0 = Xraw[r * 65 + lane];
            float x1 = Xraw[r * 65 + lane + 32];
            float s = x0 + x1;
            #pragma unroll
            for (int o = 16; o; o >>= 1) s += __shfl_xor_sync(0xffffffffu, s, o);
            float mu = s * (1.0f / 64.0f);
            float d0 = x0 - mu, d1 = x1 - mu;
            float v = d0 * d0 + d1 * d1;
            #pragma unroll
            for (int o = 16; o; o >>= 1) v += __shfl_xor_sync(0xffffffffu, v, o);
            float rinv = rsqrtf(v * (1.0f / 64.0f) + 1e-5f);
            Xs[lane * 68 + r]        = d0 * rinv * lw0 + lb0;
            Xs[(lane + 32) * 68 + r] = d1 * rinv * lw1 + lb1;
        }
        __syncthreads();

        // GEMM: 64 rows x 320 cols x 64. Thread: 4 rows x 2 cols x 5 proj.
        float acc[5][4][2];
        #pragma unroll
        for (int p = 0; p < 5; ++p)
            #pragma unroll
            for (int u = 0; u < 4; ++u) { acc[p][u][0] = 0.f; acc[p][u][1] = 0.f; }

        #pragma unroll 4
        for (int c = 0; c < 64; ++c) {
            float4 av4 = *(const float4*)&Xs[c * 68 + warp * 4];  // broadcast
            float a[4] = {av4.x, av4.y, av4.z, av4.w};
            #pragma unroll
            for (int p = 0; p < 5; ++p) {
                float w0 = Ws[p * 4096 + c * 64 + lane];
                float w1 = Ws[p * 4096 + c * 64 + lane + 32];
                #pragma unroll
                for (int u = 0; u < 4; ++u) {
                    acc[p][u][0] += a[u] * w0;
                    acc[p][u][1] += a[u] * w1;
                }
            }
        }
        __syncthreads();  // region about to be rewritten as Lt/Rt

        // Epilogue: bias, mask, gates; stage left/right transposed in smem
        #pragma unroll
        for (int u = 0; u < 4; ++u) {
            int r = warp * 4 + u;
            int k = kt * 64 + r;
            #pragma unroll
            for (int h = 0; h < 2; ++h) {
                int c = lane + h * 32;
                float lp = acc[0][u][h] + bs[c];
                float rp = acc[1][u][h] + bs[64 + c];
                float lg = acc[2][u][h] + bs[128 + c];
                float rg = acc[3][u][h] + bs[192 + c];
                float oz = acc[4][u][h] + bs[256 + c];
                Lt[c * 66 + r] = f2tf32(lp * mv * sigmoidf_(lg));
                Rt[c * 66 + r] = f2tf32(rp * mv * sigmoidf_(rg));
                g_og[(((size_t)b * LDIM + i) * LDIM + k) * CDIM + c] = sigmoidf_(oz);
            }
        }
        __syncthreads();

        // Coalesced channel-major global stores (256B per channel row)
        for (int e = tid; e < 4096; e += 512) {
            int c = e >> 6, k2 = e & 63;
            size_t cix = (((size_t)(b * 64 + c)) * LDIM + i) * LDIM + kt * 64 + k2;
            g_left[cix]  = Lt[c * 66 + k2];
            g_right[cix] = Rt[c * 66 + k2];
        }
        __syncthreads();
    }
}

// ---------------------------------------------------------------------------
// Kernel B: triangle update as 128 independent 512x512x512 NT GEMMs on the
// tensor pipe via mma.sync m16n8k8 tf32. 128x128 block tile, BK=16,
// double-buffered. 8 warps: 4 along M (32 rows each) x 2 along N (64 cols).
// Smem pitch 20 floats -> conflict-free fragment loads.
// ---------------------------------------------------------------------------
__global__ void __launch_bounds__(256, 2) kernB()
{
    __shared__ __align__(16) float As[2][128][20];
    __shared__ __align__(16) float Bs[2][128][20];

    const int m = blockIdx.z;                 // (b*64 + c)
    const float* __restrict__ Lm = g_left  + (size_t)m * (LDIM * LDIM);
    const float* __restrict__ Rm = g_right + (size_t)m * (LDIM * LDIM);
    float* __restrict__ Om       = g_tri   + (size_t)m * (LDIM * LDIM);

    const int i0 = blockIdx.y * 128;
    const int j0 = blockIdx.x * 128;
    const int tid  = threadIdx.x;
    const int lane = tid & 31;
    const int warp = tid >> 5;    // 0..7
    const int wm = warp & 3;      // M position (32 rows)
    const int wn = warp >> 2;     // N position (64 cols)
    const int g  = lane >> 2;     // group id 0..7
    const int tg = lane & 3;      // thread-in-group 0..3

    // loader coords: 512 float4 per tile; thread handles f = tid, tid+256
    const int r0 = tid >> 2, q0 = tid & 3;             // f0
    const int r1 = (tid + 256) >> 2, q1 = tid & 3;     // f1 (same q)

    float acc[2][8][4];
    #pragma unroll
    for (int t2 = 0; t2 < 2; ++t2)
        #pragma unroll
        for (int u = 0; u < 8; ++u)
            #pragma unroll
            for (int v = 0; v < 4; ++v) acc[t2][u][v] = 0.f;

    // preload stage 0
    {
        float4 a0 = *(const float4*)&Lm[(size_t)(i0 + r0) * LDIM + q0 * 4];
        float4 a1 = *(const float4*)&Lm[(size_t)(i0 + r1) * LDIM + q1 * 4];
        float4 b0 = *(const float4*)&Rm[(size_t)(j0 + r0) * LDIM + q0 * 4];
        float4 b1 = *(const float4*)&Rm[(size_t)(j0 + r1) * LDIM + q1 * 4];
        *(float4*)&As[0][r0][q0 * 4] = a0;
        *(float4*)&As[0][r1][q1 * 4] = a1;
        *(float4*)&Bs[0][r0][q0 * 4] = b0;
        *(float4*)&Bs[0][r1][q1 * 4] = b1;
    }
    __syncthreads();

    for (int t = 0; t < 32; ++t) {
        const int cur = t & 1;
        float4 pa0, pa1, pb0, pb1;
        if (t < 31) {
            int k0 = (t + 1) * 16;
            pa0 = *(const float4*)&Lm[(size_t)(i0 + r0) * LDIM + k0 + q0 * 4];
            pa1 = *(const float4*)&Lm[(size_t)(i0 + r1) * LDIM + k0 + q1 * 4];
            pb0 = *(const float4*)&Rm[(size_t)(j0 + r0) * LDIM + k0 + q0 * 4];
            pb1 = *(const float4*)&Rm[(size_t)(j0 + r1) * LDIM + k0 + q1 * 4];
        }

        #pragma unroll
        for (int kk = 0; kk < 16; kk += 8) {
            uint32_t af[2][4];
            #pragma unroll
            for (int t2 = 0; t2 < 2; ++t2) {
                const float* ap = &As[cur][wm * 32 + t2 * 16 + g][kk + tg];
                af[t2][0] = __float_as_uint(ap[0]);
                af[t2][1] = __float_as_uint(ap[8 * 20]);
                af[t2][2] = __float_as_uint(ap[4]);
                af[t2][3] = __float_as_uint(ap[8 * 20 + 4]);
            }
            uint32_t bf[8][2];
            #pragma unroll
            for (int u = 0; u < 8; ++u) {
                const float* bp = &Bs[cur][wn * 64 + u * 8 + g][kk + tg];
                bf[u][0] = __float_as_uint(bp[0]);
                bf[u][1] = __float_as_uint(bp[4]);
            }
            #pragma unroll
            for (int t2 = 0; t2 < 2; ++t2)
                #pragma unroll
                for (int u = 0; u < 8; ++u)
                    mma_tf32(acc[t2][u], af[t2], bf[u]);
        }

        if (t < 31) {
            const int nxt = cur ^ 1;
            *(float4*)&As[nxt][r0][q0 * 4] = pa0;
            *(float4*)&As[nxt][r1][q1 * 4] = pa1;
            *(float4*)&Bs[nxt][r0][q0 * 4] = pb0;
            *(float4*)&Bs[nxt][r1][q1 * 4] = pb1;
            __syncthreads();
        }
    }

    // Epilogue: D fragment layout c0,c1 @ (g, 2tg..2tg+1), c2,c3 @ (g+8, ...)
    #pragma unroll
    for (int t2 = 0; t2 < 2; ++t2) {
        #pragma unroll
        for (int u = 0; u < 8; ++u) {
            int row = i0 + wm * 32 + t2 * 16 + g;
            int col = j0 + wn * 64 + u * 8 + 2 * tg;
            float2 lo = make_float2(acc[t2][u][0], acc[t2][u][1]);
            float2 hi = make_float2(acc[t2][u][2], acc[t2][u][3]);
            *(float2*)&Om[(size_t)row * LDIM + col]       = lo;
            *(float2*)&Om[(size_t)(row + 8) * LDIM + col] = hi;
        }
    }
}

// ---------------------------------------------------------------------------
// Kernel C: y = LN(tri)*og @ W_out + b_out + residual
// ---------------------------------------------------------------------------
__global__ void __launch_bounds__(256, 2) kernC(
    const float* __restrict__ resid,
    const float* __restrict__ lnw, const float* __restrict__ lnbv,
    const float* __restrict__ Wout, const float* __restrict__ bout,
    float* __restrict__ out)
{
    extern __shared__ float sm[];
    float* Wo = sm;           // 4096
    float* bo = Wo + 4096;    // 64
    float* Tc = bo + 64;      // 64*65 = 4160  (tri gather, [c][j])
    float* Gs = Tc + 4160;    // 64*72 = 4608  (gated LN, [c][j])

    const int tid = threadIdx.x;
    const int lane = tid & 31;
    const int warp = tid >> 5;
    const int jt = blockIdx.x, i = blockIdx.y, b = blockIdx.z;

    for (int e = tid; e < 4096; e += 256) Wo[e] = Wout[e];
    if (tid < 64) bo[tid] = bout[tid];
    for (int e = tid; e < 4096; e += 256) {
        int c = e >> 6, j = e & 63;
        Tc[c * 65 + j] =
            g_tri[(((size_t)(b * 64 + c)) * LDIM + i) * LDIM + jt * 64 + j];
    }
    __syncthreads();

    const size_t rowbase = (((size_t)b * LDIM + i) * LDIM + (size_t)jt * 64) * CDIM;
    {
        const float lw0 = lnw[lane], lw1 = lnw[lane + 32];
        const float lb0 = lnbv[lane], lb1 = lnbv[lane + 32];
        #pragma unroll
        for (int u = 0; u < 8; ++u) {
            int j = warp * 8 + u;
            float t0 = Tc[lane * 65 + j];
            float t1 = Tc[(lane + 32) * 65 + j];
            float s = t0 + t1;
            #pragma unroll
            for (int o = 16; o; o >>= 1) s += __shfl_xor_sync(0xffffffffu, s, o);
            float mu = s * (1.0f / 64.0f);
            float d0 = t0 - mu, d1 = t1 - mu;
            float v = d0 * d0 + d1 * d1;
            #pragma unroll
            for (int o = 16; o; o >>= 1) v += __shfl_xor_sync(0xffffffffu, v, o);
            float rinv = rsqrtf(v * (1.0f / 64.0f) + 1e-5f);
            float g0 = (d0 * rinv * lw0 + lb0) * g_og[rowbase + (size_t)j * CDIM + lane];
            float g1 = (d1 * rinv * lw1 + lb1) * g_og[rowbase + (size_t)j * CDIM + lane + 32];
            Gs[lane * 72 + j] = g0;
            Gs[(lane + 32) * 72 + j] = g1;
        }
    }
    __syncthreads();

    float acc[8][2];
    #pragma unroll
    for (int u = 0; u < 8; ++u) { acc[u][0] = 0.f; acc[u][1] = 0.f; }

    #pragma unroll 4
    for (int c = 0; c < 64; ++c) {
        float4 a0 = *(const float4*)&Gs[c * 72 + warp * 8];
        float4 a1 = *(const float4*)&Gs[c * 72 + warp * 8 + 4];
        float a[8] = {a0.x, a0.y, a0.z, a0.w, a1.x, a1.y, a1.z, a1.w};
        float w0 = Wo[c * 64 + lane];
        float w1 = Wo[c * 64 + lane + 32];
        #pragma unroll
        for (int u = 0; u < 8; ++u) {
            acc[u][0] += a[u] * w0;
            acc[u][1] += a[u] * w1;
        }
    }

    #pragma unroll
    for (int u = 0; u < 8; ++u) {
        int j = warp * 8 + u;
        size_t o0 = rowbase + (size_t)j * CDIM + lane;
        out[o0]      = acc[u][0] + bo[lane]      + resid[o0];
        out[o0 + 32] = acc[u][1] + bo[lane + 32] + resid[o0 + 32];
    }
}

// ---------------------------------------------------------------------------

extern "C" void kernel_launch(void* const* d_in, const int* in_sizes, int n_in,
                              void* d_out, int out_size)
{
    const float* x    = (const float*)d_in[0];
    const float* msk  = (const float*)d_in[1];
    const float* liw  = (const float*)d_in[2];
    const float* lib  = (const float*)d_in[3];
    const float* Wlp  = (const float*)d_in[4];
    const float* blp  = (const float*)d_in[5];
    const float* Wrp  = (const float*)d_in[6];
    const float* brp  = (const float*)d_in[7];
    const float* Wlg  = (const float*)d_in[8];
    const float* blg  = (const float*)d_in[9];
    const float* Wrg  = (const float*)d_in[10];
    const float* brg  = (const float*)d_in[11];
    const float* Wog  = (const float*)d_in[12];
    const float* bog  = (const float*)d_in[13];
    const float* low  = (const float*)d_in[14];
    const float* lob  = (const float*)d_in[15];
    const float* Wout = (const float*)d_in[16];
    const float* bout = (const float*)d_in[17];
    float* out = (float*)d_out;

    const int SMEM_A = (20480 + 320 + 8512) * 4; // 117,248 B
    const int SMEM_C = (4096 + 64 + 4160 + 4608) * 4; // 51,712 B
    cudaFuncSetAttribute(kernA, cudaFuncAttributeMaxDynamicSharedMemorySize, SMEM_A);
    cudaFuncSetAttribute(kernC, cudaFuncAttributeMaxDynamicSharedMemorySize, SMEM_C);

    dim3 gridA(LDIM, BB);
    kernA<<<gridA, 512, SMEM_A>>>(x, msk, liw, lib,
                                  Wlp, blp, Wrp, brp, Wlg, blg, Wrg, brg, Wog, bog);

    dim3 gridB(LDIM / 128, LDIM / 128, BB * CDIM);
    kernB<<<gridB, 256>>>();

    dim3 gridC(LDIM / 64, LDIM, BB);
    kernC<<<gridC, 256, SMEM_C>>>(x, low, lob, Wout, bout, out);
}